// round 7
// baseline (speedup 1.0000x reference)
#include <cuda_runtime.h>
#include <math.h>

#define IN_F   512
#define HID    256
#define BATCH  1024

// Column-major (transposed) edge masks.
// Layer 0: column i (512 cols), 8 words of 32 output bits:   g_cmask0[i*8 + w]
// Layer 1: column j (256 cols), 16 words stored INTERLEAVED: word pair for
//          warp w = outputs {32w..} and {32(w+8)..} at g_cmask1[j*16 + 2w +0/1]
__device__ unsigned int g_cmask0[IN_F * (HID / 32)];
__device__ unsigned int g_cmask1[HID  * (IN_F / 32)];

// ---------------------------------------------------------------------------
// Kernel 1: build TRANSPOSED bitmasks. One block = one 32(o) x 32(i) tile.
// ---------------------------------------------------------------------------
__global__ __launch_bounds__(1024)
void mask_kernel(const float* __restrict__ logits0, const float* __restrict__ u0,
                 const float* __restrict__ logits1, const float* __restrict__ u1)
{
    __shared__ unsigned char tile[32][33];

    const int ty   = threadIdx.x >> 5;   // local o
    const int lane = threadIdx.x & 31;   // local i
    int bl = blockIdx.x;

    const float* L; const float* U;
    int to, ti, IN, layer;
    if (bl < 128) {         // layer 0: o in [0,256), i in [0,512)
        L = logits0; U = u0; layer = 0;
        to = bl >> 4; ti = bl & 15; IN = IN_F;
    } else {                // layer 1: o in [0,512), i in [0,256)
        bl -= 128;
        L = logits1; U = u1; layer = 1;
        to = bl >> 3; ti = bl & 7;  IN = HID;
    }

    int o = to * 32 + ty;
    int i = ti * 32 + lane;
    int e = o * IN + i;                       // float2 index (E=2)

    float2 l = reinterpret_cast<const float2*>(L)[e];
    float2 u = reinterpret_cast<const float2*>(U)[e];

    const float LO = 1e-10f;
    const float HI = 1.0f - 1e-10f;
    float ca = fminf(fmaxf(u.x, LO), HI);
    float cb = fminf(fmaxf(u.y, LO), HI);

    bool pred;
    if (l.x == l.y) {
        pred = cb > ca;                       // gumbel monotone in clipped u
    } else {
        float g0 = -logf(-logf(ca));
        float g1 = -logf(-logf(cb));
        pred = (l.y + g1) > (l.x + g0);
    }

    tile[ty][lane] = pred ? 1 : 0;
    __syncthreads();

    unsigned bit = tile[lane][ty];
    unsigned bal = __ballot_sync(0xFFFFFFFFu, bit != 0);
    if (lane == 0) {
        int col = ti * 32 + ty;               // global input index
        if (layer == 0) {
            g_cmask0[col * 8 + to] = bal;     // to in [0,8)
        } else {
            // interleave: word slot = 2*(to&7) + (to>>3), to in [0,16)
            g_cmask1[col * 16 + 2 * (to & 7) + (to >> 3)] = bal;
        }
    }
}

// ---------------------------------------------------------------------------
// 32x32 bit-matrix transpose across a warp (5 shfl_xor steps, literal masks).
// ---------------------------------------------------------------------------
__device__ __forceinline__ unsigned warp_bit_transpose(unsigned x, int lane)
{
    unsigned y;
    y = __shfl_xor_sync(0xFFFFFFFFu, x, 16);
    x = (lane & 16) ? ((x & 0xFFFF0000u) | ((y >> 16) & 0x0000FFFFu))
                    : ((x & 0x0000FFFFu) | ((y & 0x0000FFFFu) << 16));
    y = __shfl_xor_sync(0xFFFFFFFFu, x, 8);
    x = (lane & 8)  ? ((x & 0xFF00FF00u) | ((y >> 8) & 0x00FF00FFu))
                    : ((x & 0x00FF00FFu) | ((y & 0x00FF00FFu) << 8));
    y = __shfl_xor_sync(0xFFFFFFFFu, x, 4);
    x = (lane & 4)  ? ((x & 0xF0F0F0F0u) | ((y >> 4) & 0x0F0F0F0Fu))
                    : ((x & 0x0F0F0F0Fu) | ((y & 0x0F0F0F0Fu) << 4));
    y = __shfl_xor_sync(0xFFFFFFFFu, x, 2);
    x = (lane & 2)  ? ((x & 0xCCCCCCCCu) | ((y >> 2) & 0x33333333u))
                    : ((x & 0x33333333u) | ((y & 0x33333333u) << 2));
    y = __shfl_xor_sync(0xFFFFFFFFu, x, 1);
    x = (lane & 1)  ? ((x & 0xAAAAAAAAu) | ((y >> 1) & 0x55555555u))
                    : ((x & 0x55555555u) | ((y & 0x55555555u) << 1));
    return x;
}

// One window step of the first-hit walk for one output (exact tie rescan).
__device__ __forceinline__ void walk_step(
    float& v, unsigned& q, bool& done, bool& pend,
    unsigned hits, const unsigned* __restrict__ keys,   // skey + base
    const float* __restrict__ vals, unsigned lastb, bool isMin)
{
    unsigned scanb = 0;
    if (!done) {
        if (hits) {
            int p = __ffs(hits) - 1;
            unsigned k0 = keys[p];
            q = k0 >> 9;
            v = vals[k0 & 511u];
            done = true; pend = true;
            scanb = hits & (0xFFFFFFFEu << p);          // bits strictly > p
        }
    } else if (pend) {
        scanb = hits;
    }
    while (scanb) {                                      // same-bucket rescan
        int p2 = __ffs(scanb) - 1;
        scanb &= scanb - 1;
        unsigned k2 = keys[p2];
        if ((k2 >> 9) != q) { pend = false; break; }
        float u = vals[k2 & 511u];
        v = isMin ? fminf(v, u) : fmaxf(v, u);
    }
    if (pend) pend = (lastb == q);                       // bucket spills on?
}

// ---------------------------------------------------------------------------
// Kernel 2: fused two-layer evaluation, one block per batch row.
// Counting sort + warp-local bit-parallel first-hit walk (see round 6).
// ---------------------------------------------------------------------------
__global__ __launch_bounds__(256)
void row_kernel(const float* __restrict__ x, float* __restrict__ out)
{
    __shared__ unsigned cnt[IN_F];    // counts, then exclusive offsets
    __shared__ unsigned skey[IN_F];   // sorted keys: (bucket<<9)|idx
    __shared__ float    sval[IN_F];   // exact x row
    __shared__ float    shv[HID];     // exact h row
    __shared__ unsigned wsum[8];

    const int b    = blockIdx.x;
    const int t    = threadIdx.x;     // 0..255
    const int lane = t & 31;
    const int w    = t >> 5;

    // ============ layer 0 sort: counting sort of x (512 linear buckets) ====
    cnt[t] = 0; cnt[t + 256] = 0;
    float v0 = x[b * IN_F + t];
    float v1 = x[b * IN_F + t + 256];
    sval[t] = v0; sval[t + 256] = v1;
    __syncthreads();

    int b0 = min((int)(v0 * 512.0f), 511);   // exact pow2 scaling -> monotone
    int b1 = min((int)(v1 * 512.0f), 511);
    unsigned r0 = atomicAdd(&cnt[b0], 1u);
    unsigned r1 = atomicAdd(&cnt[b1], 1u);
    __syncthreads();

    unsigned c0 = cnt[2 * t], c1 = cnt[2 * t + 1];
    unsigned s  = c0 + c1, sc = s;
#pragma unroll
    for (int d = 1; d < 32; d <<= 1) {
        unsigned o = __shfl_up_sync(0xFFFFFFFFu, sc, d);
        if (lane >= d) sc += o;
    }
    if (lane == 31) wsum[w] = sc;
    __syncthreads();
    unsigned wexcl = 0;
#pragma unroll
    for (int i = 0; i < 8; i++) if (i < w) wexcl += wsum[i];
    unsigned excl = wexcl + (sc - s);
    cnt[2 * t]     = excl;
    cnt[2 * t + 1] = excl + c0;
    __syncthreads();

    skey[cnt[b0] + r0] = ((unsigned)b0 << 9) | (unsigned)t;
    skey[cnt[b1] + r1] = ((unsigned)b1 << 9) | (unsigned)(t + 256);
    __syncthreads();

    // ===== layer 0 bit-parallel walk: warp w owns outputs 32w..32w+31 ======
    float h = 1.0f;                   // default: no selected edge
    {
        bool done = false, pend = false;
        unsigned qb = 0;
        for (int base = 0; base < IN_F; base += 32) {
            unsigned keyl  = skey[base + lane];
            unsigned lastb = __shfl_sync(0xFFFFFFFFu, keyl, 31) >> 9;
            unsigned col   = g_cmask0[(keyl & 511u) * 8 + w];
            unsigned hits  = warp_bit_transpose(col, lane);
            walk_step(h, qb, done, pend, hits, skey + base, sval, lastb, true);
            if (__all_sync(0xFFFFFFFFu, done && !pend)) break;
        }
    }
    __syncthreads();                  // all walks read skey/sval before reuse

    // ====== layer 1 sort: counting sort of h, LOG buckets, descending ======
    shv[t] = h;
    cnt[t] = 0;
    __syncthreads();

    // bucket = clamp((hbits>>19)-1792, 0, 255): exp + top-4 mantissa bits,
    // monotone in h >= 0; h <= 1.0 -> bucket <= 240.
    unsigned hb  = __float_as_uint(h);
    int bkt = min(max((int)(hb >> 19) - 1792, 0), 255);
    int bd  = 255 - bkt;              // descending
    unsigned rr = atomicAdd(&cnt[bd], 1u);
    __syncthreads();

    unsigned c = cnt[t], scn = c;
#pragma unroll
    for (int d = 1; d < 32; d <<= 1) {
        unsigned o = __shfl_up_sync(0xFFFFFFFFu, scn, d);
        if (lane >= d) scn += o;
    }
    if (lane == 31) wsum[w] = scn;
    __syncthreads();
    unsigned wex = 0;
#pragma unroll
    for (int i = 0; i < 8; i++) if (i < w) wex += wsum[i];
    cnt[t] = wex + scn - c;
    __syncthreads();

    skey[cnt[bd] + rr] = ((unsigned)bd << 9) | (unsigned)t;
    __syncthreads();

    // == layer 1 walk: warp w owns output words for o=t (a) and o=t+256 (b) =
    float ra = 0.0f, rb = 0.0f;       // default: no selected edge
    {
        bool da = false, pa = false, db = false, pb = false;
        unsigned qa = 0, qv = 0;
        const uint2* __restrict__ cm1 = reinterpret_cast<const uint2*>(g_cmask1);
        for (int base = 0; base < HID; base += 32) {
            unsigned keyl  = skey[base + lane];
            unsigned lastb = __shfl_sync(0xFFFFFFFFu, keyl, 31) >> 9;
            uint2 cw = cm1[(keyl & 511u) * 8 + w];       // one LDG.64
            unsigned hta = warp_bit_transpose(cw.x, lane);
            unsigned htb = warp_bit_transpose(cw.y, lane);
            walk_step(ra, qa, da, pa, hta, skey + base, shv, lastb, false);
            walk_step(rb, qv, db, pb, htb, skey + base, shv, lastb, false);
            if (__all_sync(0xFFFFFFFFu, da && !pa && db && !pb)) break;
        }
    }

    out[b * IN_F + t]       = ra;
    out[b * IN_F + t + 256] = rb;
}

// ---------------------------------------------------------------------------
// kernel_launch: graph-capturable, allocation-free.
// Inputs: x, logits0, u0, logits1, u1. Output: float32 [1024,512].
// ---------------------------------------------------------------------------
extern "C" void kernel_launch(void* const* d_in, const int* in_sizes, int n_in,
                              void* d_out, int out_size)
{
    const float* x       = (const float*)d_in[0];
    const float* logits0 = (const float*)d_in[1];
    const float* u0      = (const float*)d_in[2];
    const float* logits1 = (const float*)d_in[3];
    const float* u1      = (const float*)d_in[4];
    float* out = (float*)d_out;

    mask_kernel<<<256, 1024>>>(logits0, u0, logits1, u1);
    row_kernel<<<BATCH, 256>>>(x, out);
}